// round 2
// baseline (speedup 1.0000x reference)
#include <cuda_runtime.h>
#include <math.h>
#include <float.h>

#define HN 16
#define SQ 2048
#define DM 2048
#define DH 128

// ---------------- scratch (static device arrays: no allocation allowed) ----
__device__ float g_q[HN * SQ * DH];     // head-major [H][S][DH]
__device__ float g_k[HN * SQ * DH];
__device__ float g_v[HN * SQ * DH];
__device__ float g_attn[SQ * DM];       // [S][H*DH] row-major

// ---------------- shared GEMM body: C = A * B^T, M=N=K=2048 ----------------
// BM=BN=128, BK=16, 256 threads, 8x8 micro-tile, 2-stage smem double buffer.
// HEAD=true: scatter C[m][n] to dst[h][m][jj] head-major (h=n>>7, jj=n&127).
template <bool HEAD>
__device__ __forceinline__ void gemm_body(const float* __restrict__ A,
                                          const float* __restrict__ Bw,
                                          float* __restrict__ dst) {
    __shared__ float As[2][16][132];
    __shared__ float Bs[2][16][132];

    const int tid = threadIdx.x;
    const int ty  = tid >> 4;     // 0..15
    const int tx  = tid & 15;     // 0..15
    const int m0  = blockIdx.y * 128;
    const int n0  = blockIdx.x * 128;

    const int lr  = tid >> 2;     // load row 0..63 (rows lr and lr+64)
    const int lc4 = tid & 3;      // float4-col 0..3
    const int lc  = lc4 * 4;

    float acc[8][8];
#pragma unroll
    for (int i = 0; i < 8; i++)
#pragma unroll
        for (int j = 0; j < 8; j++) acc[i][j] = 0.f;

    const float* Arow0 = A  + (size_t)(m0 + lr) * DM + lc;
    const float* Arow1 = A  + (size_t)(m0 + lr + 64) * DM + lc;
    const float* Brow0 = Bw + (size_t)(n0 + lr) * DM + lc;
    const float* Brow1 = Bw + (size_t)(n0 + lr + 64) * DM + lc;

    // preload first K-slab into stage 0
    {
        float4 a0 = *(const float4*)Arow0;
        float4 a1 = *(const float4*)Arow1;
        float4 b0 = *(const float4*)Brow0;
        float4 b1 = *(const float4*)Brow1;
        As[0][lc + 0][lr] = a0.x; As[0][lc + 1][lr] = a0.y;
        As[0][lc + 2][lr] = a0.z; As[0][lc + 3][lr] = a0.w;
        As[0][lc + 0][lr + 64] = a1.x; As[0][lc + 1][lr + 64] = a1.y;
        As[0][lc + 2][lr + 64] = a1.z; As[0][lc + 3][lr + 64] = a1.w;
        Bs[0][lc + 0][lr] = b0.x; Bs[0][lc + 1][lr] = b0.y;
        Bs[0][lc + 2][lr] = b0.z; Bs[0][lc + 3][lr] = b0.w;
        Bs[0][lc + 0][lr + 64] = b1.x; Bs[0][lc + 1][lr + 64] = b1.y;
        Bs[0][lc + 2][lr + 64] = b1.z; Bs[0][lc + 3][lr + 64] = b1.w;
    }
    __syncthreads();

    int stage = 0;
    for (int k0 = 0; k0 < DM; k0 += 16) {
        const bool more = (k0 + 16) < DM;
        float4 pa0, pa1, pb0, pb1;
        if (more) {
            // issue next slab's global loads up-front; they complete while we
            // run the 1024-FFMA burst below.
            pa0 = *(const float4*)(Arow0 + k0 + 16);
            pa1 = *(const float4*)(Arow1 + k0 + 16);
            pb0 = *(const float4*)(Brow0 + k0 + 16);
            pb1 = *(const float4*)(Brow1 + k0 + 16);
        }

#pragma unroll
        for (int k = 0; k < 16; k++) {
            float a[8], b[8];
            *(float4*)&a[0] = *(const float4*)&As[stage][k][ty * 8];
            *(float4*)&a[4] = *(const float4*)&As[stage][k][ty * 8 + 4];
            *(float4*)&b[0] = *(const float4*)&Bs[stage][k][tx * 4];
            *(float4*)&b[4] = *(const float4*)&Bs[stage][k][64 + tx * 4];
#pragma unroll
            for (int i = 0; i < 8; i++)
#pragma unroll
                for (int j = 0; j < 8; j++)
                    acc[i][j] = fmaf(a[i], b[j], acc[i][j]);
        }

        if (more) {
            const int ns = stage ^ 1;
            As[ns][lc + 0][lr] = pa0.x; As[ns][lc + 1][lr] = pa0.y;
            As[ns][lc + 2][lr] = pa0.z; As[ns][lc + 3][lr] = pa0.w;
            As[ns][lc + 0][lr + 64] = pa1.x; As[ns][lc + 1][lr + 64] = pa1.y;
            As[ns][lc + 2][lr + 64] = pa1.z; As[ns][lc + 3][lr + 64] = pa1.w;
            Bs[ns][lc + 0][lr] = pb0.x; Bs[ns][lc + 1][lr] = pb0.y;
            Bs[ns][lc + 2][lr] = pb0.z; Bs[ns][lc + 3][lr] = pb0.w;
            Bs[ns][lc + 0][lr + 64] = pb1.x; Bs[ns][lc + 1][lr + 64] = pb1.y;
            Bs[ns][lc + 2][lr + 64] = pb1.z; Bs[ns][lc + 3][lr + 64] = pb1.w;
            __syncthreads();
            stage = ns;
        }
    }

#pragma unroll
    for (int i = 0; i < 8; i++) {
        const int m = m0 + ty * 8 + i;
#pragma unroll
        for (int j = 0; j < 8; j++) {
            const int n = n0 + (j < 4 ? tx * 4 + j : 64 + tx * 4 + (j - 4));
            if (HEAD) {
                const int h = n >> 7, jj = n & 127;
                dst[((size_t)h * SQ + m) * DH + jj] = acc[i][j];
            } else {
                dst[(size_t)m * DM + n] = acc[i][j];
            }
        }
    }
}

__global__ __launch_bounds__(256) void gemm_qkv(const float* __restrict__ x,
                                                const float* __restrict__ wq,
                                                const float* __restrict__ wk,
                                                const float* __restrict__ wv) {
    const int z = blockIdx.z;
    const float* Bw = (z == 0) ? wq : (z == 1) ? wk : wv;
    float* dst      = (z == 0) ? g_q : (z == 1) ? g_k : g_v;
    gemm_body<true>(x, Bw, dst);
}

__global__ __launch_bounds__(256) void gemm_out(const float* __restrict__ wo,
                                                float* __restrict__ out) {
    gemm_body<false>(g_attn, wo, out);
}

// ---------------- RoPE (in-place on g_q, g_k) ------------------------------
// cos/sin are [S][128] with duplicated halves: cos[s][j] == cos[s][j+64].
__global__ void rope_kernel(const float* __restrict__ cosp,
                            const float* __restrict__ sinp) {
    const int idx = blockIdx.x * blockDim.x + threadIdx.x;  // 2*16*2048*64 total
    const int j     = idx & 63;
    const int s     = (idx >> 6) & (SQ - 1);
    const int h     = (idx >> 17) & 15;
    const int which = idx >> 21;
    float* p = (which ? g_k : g_q) + ((size_t)h * SQ + s) * DH;
    const float c  = cosp[s * DH + j];
    const float sn = sinp[s * DH + j];
    const float x1 = p[j], x2 = p[j + 64];
    p[j]      = x1 * c - x2 * sn;
    p[j + 64] = x2 * c + x1 * sn;
}

// ---------------- flash attention (causal, tanh softcap 50) ----------------
// BM=BN=128, 256 threads (16x16), 8x8 per thread for scores and O.
// smem: Qs[128][132] (d-major), KPs[128][132] (K tile d-major, reused as P
// tile n-major), Vs[128][128].
#define FLASH_SMEM_FLOATS (2 * 128 * 132 + 128 * 128)
#define FLASH_SMEM_BYTES  (FLASH_SMEM_FLOATS * 4)

__device__ __forceinline__ float rmax16(float v) {
#pragma unroll
    for (int o = 8; o; o >>= 1) v = fmaxf(v, __shfl_xor_sync(0xffffffffu, v, o));
    return v;
}
__device__ __forceinline__ float rsum16(float v) {
#pragma unroll
    for (int o = 8; o; o >>= 1) v += __shfl_xor_sync(0xffffffffu, v, o);
    return v;
}

__global__ __launch_bounds__(256) void flash_kernel() {
    extern __shared__ float sm[];
    float* Qs  = sm;                     // [128][132], Qs[d][r]
    float* KPs = sm + 128 * 132;         // K: KPs[d][n]   /  P: KPs[n][r]
    float* Vs  = sm + 2 * 128 * 132;     // [128][128], Vs[n][d]

    const int tid = threadIdx.x;
    const int ty  = tid >> 4;            // 0..15 -> rows ty*8..+7
    const int tx  = tid & 15;            // cols tx*4 and 64+tx*4
    const int h   = blockIdx.y;
    const int qb  = (int)gridDim.x - 1 - (int)blockIdx.x;  // heavy blocks first
    const int q0  = qb * 128;

    // load Q tile (transposed into smem)
    const float* Qg = g_q + ((size_t)h * SQ + q0) * DH;
#pragma unroll
    for (int t = 0; t < 16; t++) {
        const int id = tid + t * 256;
        const int r = id >> 5, j4 = id & 31;
        float4 v = *(const float4*)&Qg[(size_t)r * DH + j4 * 4];
        const int j = j4 * 4;
        Qs[(j + 0) * 132 + r] = v.x; Qs[(j + 1) * 132 + r] = v.y;
        Qs[(j + 2) * 132 + r] = v.z; Qs[(j + 3) * 132 + r] = v.w;
    }

    float m_[8], l_[8], o_[8][8];
#pragma unroll
    for (int i = 0; i < 8; i++) {
        m_[i] = -1e30f; l_[i] = 0.f;
#pragma unroll
        for (int j = 0; j < 8; j++) o_[i][j] = 0.f;
    }

    const float SCALE = 0.08838834764831845f;  // 1/sqrt(128)

    for (int ck = 0; ck <= qb; ck++) {
        const float* Kg = g_k + ((size_t)h * SQ + ck * 128) * DH;
        const float* Vg = g_v + ((size_t)h * SQ + ck * 128) * DH;
        // K transposed, V natural
#pragma unroll
        for (int t = 0; t < 16; t++) {
            const int id = tid + t * 256;
            const int r = id >> 5, j4 = id & 31;
            float4 v = *(const float4*)&Kg[(size_t)r * DH + j4 * 4];
            const int j = j4 * 4;
            KPs[(j + 0) * 132 + r] = v.x; KPs[(j + 1) * 132 + r] = v.y;
            KPs[(j + 2) * 132 + r] = v.z; KPs[(j + 3) * 132 + r] = v.w;
            float4 w = *(const float4*)&Vg[(size_t)r * DH + j4 * 4];
            *(float4*)&Vs[r * 128 + j4 * 4] = w;
        }
        __syncthreads();

        // scores S = Q K^T  (8x8 per thread)
        float s_[8][8];
#pragma unroll
        for (int i = 0; i < 8; i++)
#pragma unroll
            for (int j = 0; j < 8; j++) s_[i][j] = 0.f;

        for (int d = 0; d < 128; d++) {
            float a[8], b[8];
            *(float4*)&a[0] = *(const float4*)&Qs[d * 132 + ty * 8];
            *(float4*)&a[4] = *(const float4*)&Qs[d * 132 + ty * 8 + 4];
            *(float4*)&b[0] = *(const float4*)&KPs[d * 132 + tx * 4];
            *(float4*)&b[4] = *(const float4*)&KPs[d * 132 + 64 + tx * 4];
#pragma unroll
            for (int i = 0; i < 8; i++)
#pragma unroll
                for (int j = 0; j < 8; j++)
                    s_[i][j] = fmaf(a[i], b[j], s_[i][j]);
        }

        // scale, tanh softcap, causal mask (diagonal chunk only)
        const bool diag = (ck == qb);
#pragma unroll
        for (int i = 0; i < 8; i++) {
#pragma unroll
            for (int j = 0; j < 8; j++) {
                float v = s_[i][j] * SCALE;
                v = 50.f * tanhf(v * 0.02f);
                if (diag) {
                    const int qg = ty * 8 + i;
                    const int kg = (j < 4 ? tx * 4 + j : 64 + tx * 4 + (j - 4));
                    if (kg > qg) v = -1e30f;
                }
                s_[i][j] = v;
            }
        }

        // online softmax (row stats across the 16 lanes sharing each row)
#pragma unroll
        for (int i = 0; i < 8; i++) {
            float mx = s_[i][0];
#pragma unroll
            for (int j = 1; j < 8; j++) mx = fmaxf(mx, s_[i][j]);
            mx = rmax16(mx);
            const float nm    = fmaxf(m_[i], mx);
            const float alpha = __expf(m_[i] - nm);
            float rs = 0.f;
#pragma unroll
            for (int j = 0; j < 8; j++) {
                const float p = __expf(s_[i][j] - nm);
                s_[i][j] = p;
                rs += p;
            }
            rs = rsum16(rs);
            l_[i] = l_[i] * alpha + rs;
            m_[i] = nm;
#pragma unroll
            for (int j = 0; j < 8; j++) o_[i][j] *= alpha;
        }

        __syncthreads();   // everyone done reading K tile
        // store P (n-major) into the K buffer
#pragma unroll
        for (int i = 0; i < 8; i++) {
            const int r = ty * 8 + i;
#pragma unroll
            for (int j = 0; j < 8; j++) {
                const int c = (j < 4 ? tx * 4 + j : 64 + tx * 4 + (j - 4));
                KPs[c * 132 + r] = s_[i][j];
            }
        }
        __syncthreads();

        // O += P V
        for (int n = 0; n < 128; n++) {
            float a[8], b[8];
            *(float4*)&a[0] = *(const float4*)&KPs[n * 132 + ty * 8];
            *(float4*)&a[4] = *(const float4*)&KPs[n * 132 + ty * 8 + 4];
            *(float4*)&b[0] = *(const float4*)&Vs[n * 128 + tx * 4];
            *(float4*)&b[4] = *(const float4*)&Vs[n * 128 + 64 + tx * 4];
#pragma unroll
            for (int i = 0; i < 8; i++)
#pragma unroll
                for (int j = 0; j < 8; j++)
                    o_[i][j] = fmaf(a[i], b[j], o_[i][j]);
        }
        __syncthreads();   // before next chunk overwrites K/V tiles
    }

    // normalize + write to [S][H*DH]
    float* Og = g_attn + (size_t)q0 * DM + h * DH;
#pragma unroll
    for (int i = 0; i < 8; i++) {
        const float inv = 1.f / l_[i];
        const int r = ty * 8 + i;
#pragma unroll
        for (int j = 0; j < 8; j++) {
            const int dcol = (j < 4 ? tx * 4 + j : 64 + tx * 4 + (j - 4));
            Og[(size_t)r * DM + dcol] = o_[i][j] * inv;
        }
    }
}

// ---------------- launch ----------------------------------------------------
extern "C" void kernel_launch(void* const* d_in, const int* in_sizes, int n_in,
                              void* d_out, int out_size) {
    (void)in_sizes; (void)n_in; (void)out_size;
    const float* x  = (const float*)d_in[0];
    const float* rc = (const float*)d_in[1];
    const float* rs = (const float*)d_in[2];
    // d_in[3] = mask: exactly causal -1e9; implemented directly in-kernel.
    const float* wq = (const float*)d_in[4];
    const float* wk = (const float*)d_in[5];
    const float* wv = (const float*)d_in[6];
    const float* wo = (const float*)d_in[7];
    float* out = (float*)d_out;

    gemm_qkv<<<dim3(16, 16, 3), 256>>>(x, wq, wk, wv);
    rope_kernel<<<(2 * HN * SQ * 64) / 256, 256>>>(rc, rs);

    cudaFuncSetAttribute(flash_kernel,
                         cudaFuncAttributeMaxDynamicSharedMemorySize,
                         FLASH_SMEM_BYTES);
    flash_kernel<<<dim3(16, 16), 256, FLASH_SMEM_BYTES>>>();

    gemm_out<<<dim3(16, 16), 256>>>(wo, out);
}

// round 12
// speedup vs baseline: 1.9490x; 1.9490x over previous
#include <cuda_runtime.h>
#include <cuda_bf16.h>
#include <math.h>
#include <float.h>

#define HN 16
#define SQ 2048
#define DM 2048
#define DH 128

// ---------------- scratch (static device arrays: no allocation allowed) ----
__device__ float g_q[HN * SQ * DH];     // head-major [H][S][DH]
__device__ float g_k[HN * SQ * DH];
__device__ float g_v[HN * SQ * DH];
__device__ float g_attn[SQ * DM];       // [S][H*DH] row-major

// ============================================================================
// Common MMA / conversion primitives (bf16x3 split arithmetic)
// ============================================================================

__device__ __forceinline__ void ldsm4(unsigned& r0, unsigned& r1,
                                      unsigned& r2, unsigned& r3, unsigned addr) {
    asm volatile("ldmatrix.sync.aligned.m8n8.x4.shared.b16 {%0,%1,%2,%3}, [%4];"
                 : "=r"(r0), "=r"(r1), "=r"(r2), "=r"(r3) : "r"(addr));
}
__device__ __forceinline__ void ldsm2(unsigned& r0, unsigned& r1, unsigned addr) {
    asm volatile("ldmatrix.sync.aligned.m8n8.x2.shared.b16 {%0,%1}, [%2];"
                 : "=r"(r0), "=r"(r1) : "r"(addr));
}
__device__ __forceinline__ void mma16816(float c[4], const unsigned a[4],
                                         const unsigned b[2]) {
    asm volatile(
        "mma.sync.aligned.m16n8k16.row.col.f32.bf16.bf16.f32 "
        "{%0,%1,%2,%3}, {%4,%5,%6,%7}, {%8,%9}, {%0,%1,%2,%3};"
        : "+f"(c[0]), "+f"(c[1]), "+f"(c[2]), "+f"(c[3])
        : "r"(a[0]), "r"(a[1]), "r"(a[2]), "r"(a[3]), "r"(b[0]), "r"(b[1]));
}

// split two fp32 into packed bf16x2 hi and lo (x = hi + lo, split exact)
__device__ __forceinline__ void split2(float x0, float x1,
                                       unsigned& hi, unsigned& lo) {
    __nv_bfloat16 h0 = __float2bfloat16_rn(x0);
    __nv_bfloat16 h1 = __float2bfloat16_rn(x1);
    __nv_bfloat16 l0 = __float2bfloat16_rn(x0 - __bfloat162float(h0));
    __nv_bfloat16 l1 = __float2bfloat16_rn(x1 - __bfloat162float(h1));
    hi = (unsigned)__bfloat16_as_ushort(h0) |
         ((unsigned)__bfloat16_as_ushort(h1) << 16);
    lo = (unsigned)__bfloat16_as_ushort(l0) |
         ((unsigned)__bfloat16_as_ushort(l1) << 16);
}

// convert 8 fp32 -> 16B hi-plane + 16B lo-plane stores
__device__ __forceinline__ void cvt_sts(const float4 f0, const float4 f1,
                                        char* hip, char* lop) {
    float f[8] = {f0.x, f0.y, f0.z, f0.w, f1.x, f1.y, f1.z, f1.w};
    unsigned h[4], l[4];
#pragma unroll
    for (int i = 0; i < 4; i++) split2(f[2 * i], f[2 * i + 1], h[i], l[i]);
    *(uint4*)hip = make_uint4(h[0], h[1], h[2], h[3]);
    *(uint4*)lop = make_uint4(l[0], l[1], l[2], l[3]);
}

// ============================================================================
// bf16x3 tensor-core GEMM: C = A * B^T, M=N=K=2048, fp32 in/out.
// CTA tile 128x128, BK=32, 256 threads = 8 warps (2 m x 4 n), warp tile 64x32.
// Planes: [128 rows][32 bf16 = 64B], 16B chunks XOR-swizzled:
// phys_chunk = chunk ^ ((row>>1)&3). Double buffered (64KB).
// ============================================================================

#define STAGE_BYTES 32768
#define PLANE_A_HI 0
#define PLANE_A_LO 8192
#define PLANE_B_HI 16384
#define PLANE_B_LO 24576
#define GEMM_SMEM_BYTES (2 * STAGE_BYTES)

// HEAD=true: scatter C[m][n] to dst[h][m][jj], h=n>>7, jj=n&127.
template <bool HEAD>
__device__ __forceinline__ void gemm_body_mma(const float* __restrict__ A,
                                              const float* __restrict__ Bw,
                                              float* __restrict__ dst) {
    extern __shared__ char smem[];
    const int tid  = threadIdx.x;
    const int lane = tid & 31;
    const int w    = tid >> 5;
    const int wm   = w & 1;        // 2 warps along M
    const int wn   = w >> 1;       // 4 warps along N
    const int m0   = blockIdx.y * 128;
    const int n0   = blockIdx.x * 128;

    const int r0 = tid >> 2,          c0 = tid & 3;
    const int r1 = (tid + 256) >> 2,  c1 = (tid + 256) & 3;
    const float* Ag0 = A  + (size_t)(m0 + r0) * DM + c0 * 8;
    const float* Ag1 = A  + (size_t)(m0 + r1) * DM + c1 * 8;
    const float* Bg0 = Bw + (size_t)(n0 + r0) * DM + c0 * 8;
    const float* Bg1 = Bw + (size_t)(n0 + r1) * DM + c1 * 8;
    const int so0 = r0 * 64 + ((c0 ^ ((r0 >> 1) & 3)) << 4);
    const int so1 = r1 * 64 + ((c1 ^ ((r1 >> 1) & 3)) << 4);

    float acc[4][4][4];
#pragma unroll
    for (int i = 0; i < 4; i++)
#pragma unroll
        for (int j = 0; j < 4; j++)
#pragma unroll
            for (int k = 0; k < 4; k++) acc[i][j][k] = 0.f;

    float4 va0a, va0b, va1a, va1b, vb0a, vb0b, vb1a, vb1b;

    va0a = *(const float4*)(Ag0);     va0b = *(const float4*)(Ag0 + 4);
    va1a = *(const float4*)(Ag1);     va1b = *(const float4*)(Ag1 + 4);
    vb0a = *(const float4*)(Bg0);     vb0b = *(const float4*)(Bg0 + 4);
    vb1a = *(const float4*)(Bg1);     vb1b = *(const float4*)(Bg1 + 4);
    cvt_sts(va0a, va0b, smem + PLANE_A_HI + so0, smem + PLANE_A_LO + so0);
    cvt_sts(va1a, va1b, smem + PLANE_A_HI + so1, smem + PLANE_A_LO + so1);
    cvt_sts(vb0a, vb0b, smem + PLANE_B_HI + so0, smem + PLANE_B_LO + so0);
    cvt_sts(vb1a, vb1b, smem + PLANE_B_HI + so1, smem + PLANE_B_LO + so1);
    __syncthreads();

    const unsigned sbase = (unsigned)__cvta_generic_to_shared(smem);

    for (int k0 = 0; k0 < DM; k0 += 32) {
        const int  s    = (k0 >> 5) & 1;
        const bool more = (k0 + 32) < DM;
        if (more) {
            va0a = *(const float4*)(Ag0 + k0 + 32);
            va0b = *(const float4*)(Ag0 + k0 + 36);
            va1a = *(const float4*)(Ag1 + k0 + 32);
            va1b = *(const float4*)(Ag1 + k0 + 36);
            vb0a = *(const float4*)(Bg0 + k0 + 32);
            vb0b = *(const float4*)(Bg0 + k0 + 36);
            vb1a = *(const float4*)(Bg1 + k0 + 32);
            vb1b = *(const float4*)(Bg1 + k0 + 36);
        }
        const unsigned sA = sbase + s * STAGE_BYTES;

#pragma unroll
        for (int ks = 0; ks < 2; ks++) {
            unsigned bhi[4][2], blo[4][2];
#pragma unroll
            for (int nt = 0; nt < 4; nt++) {
                const int row = wn * 32 + nt * 8 + (lane & 7);
                const int ch  = ks * 2 + ((lane >> 3) & 1);
                const int off = row * 64 + ((ch ^ ((row >> 1) & 3)) << 4);
                ldsm2(bhi[nt][0], bhi[nt][1], sA + PLANE_B_HI + off);
                ldsm2(blo[nt][0], blo[nt][1], sA + PLANE_B_LO + off);
            }
#pragma unroll
            for (int mt = 0; mt < 4; mt++) {
                const int row = wm * 64 + mt * 16 + (lane & 15);
                const int ch  = ks * 2 + (lane >> 4);
                const int off = row * 64 + ((ch ^ ((row >> 1) & 3)) << 4);
                unsigned ahi[4], alo[4];
                ldsm4(ahi[0], ahi[1], ahi[2], ahi[3], sA + PLANE_A_HI + off);
                ldsm4(alo[0], alo[1], alo[2], alo[3], sA + PLANE_A_LO + off);
#pragma unroll
                for (int nt = 0; nt < 4; nt++) {
                    mma16816(acc[mt][nt], ahi, bhi[nt]);
                    mma16816(acc[mt][nt], ahi, blo[nt]);
                    mma16816(acc[mt][nt], alo, bhi[nt]);
                }
            }
        }

        if (more) {
            char* nb = smem + (s ^ 1) * STAGE_BYTES;
            cvt_sts(va0a, va0b, nb + PLANE_A_HI + so0, nb + PLANE_A_LO + so0);
            cvt_sts(va1a, va1b, nb + PLANE_A_HI + so1, nb + PLANE_A_LO + so1);
            cvt_sts(vb0a, vb0b, nb + PLANE_B_HI + so0, nb + PLANE_B_LO + so0);
            cvt_sts(vb1a, vb1b, nb + PLANE_B_HI + so1, nb + PLANE_B_LO + so1);
            __syncthreads();
        }
    }

#pragma unroll
    for (int mt = 0; mt < 4; mt++) {
        const int row = m0 + wm * 64 + mt * 16 + (lane >> 2);
#pragma unroll
        for (int nt = 0; nt < 4; nt++) {
            const int n = n0 + wn * 32 + nt * 8 + 2 * (lane & 3);
            const float2 v01 = make_float2(acc[mt][nt][0], acc[mt][nt][1]);
            const float2 v23 = make_float2(acc[mt][nt][2], acc[mt][nt][3]);
            if (HEAD) {
                const int h = n >> 7, jj = n & 127;
                *(float2*)&dst[((size_t)h * SQ + row) * DH + jj]     = v01;
                *(float2*)&dst[((size_t)h * SQ + row + 8) * DH + jj] = v23;
            } else {
                *(float2*)&dst[(size_t)row * DM + n]       = v01;
                *(float2*)&dst[(size_t)(row + 8) * DM + n] = v23;
            }
        }
    }
}

__global__ __launch_bounds__(256) void gemm_qkv(const float* __restrict__ x,
                                                const float* __restrict__ wq,
                                                const float* __restrict__ wk,
                                                const float* __restrict__ wv) {
    const int z = blockIdx.z;
    const float* Bw = (z == 0) ? wq : (z == 1) ? wk : wv;
    float* dst      = (z == 0) ? g_q : (z == 1) ? g_k : g_v;
    gemm_body_mma<true>(x, Bw, dst);
}

__global__ __launch_bounds__(256) void gemm_out(const float* __restrict__ wo,
                                                float* __restrict__ out) {
    gemm_body_mma<false>(g_attn, wo, out);
}

// ---------------- RoPE (in-place on g_q, g_k) ------------------------------
__global__ void rope_kernel(const float* __restrict__ cosp,
                            const float* __restrict__ sinp) {
    const int idx = blockIdx.x * blockDim.x + threadIdx.x;
    const int j     = idx & 63;
    const int s     = (idx >> 6) & (SQ - 1);
    const int h     = (idx >> 17) & 15;
    const int which = idx >> 21;
    float* p = (which ? g_k : g_q) + ((size_t)h * SQ + s) * DH;
    const float c  = cosp[s * DH + j];
    const float sn = sinp[s * DH + j];
    const float x1 = p[j], x2 = p[j + 64];
    p[j]      = x1 * c - x2 * sn;
    p[j + 64] = x2 * c + x1 * sn;
}

// ============================================================================
// Tensor-core flash attention (causal, tanh softcap 50), bf16x3 on S and PV.
// BM=128 q-rows/CTA, 128 keys/iter, 8 warps x (16q x 128k) warp tiles.
// Softmax fully in registers; P repacked c-frag -> A-frag (no smem).
// Planes (4 slabs of [128 rows][64B], XOR swizzle as in GEMM):
//   Q hi/lo (rows=q, cols=d), K hi/lo (rows=key, cols=d),
//   V^T hi/lo (rows=d, cols=key).
// ============================================================================

#define F_Q_HI 0
#define F_Q_LO 32768
#define F_K_HI 65536
#define F_K_LO 98304
#define F_V_HI 131072
#define F_V_LO 163840
#define FLASH2_SMEM 196608

// [128 rows][128 cols] fp32 tile -> hi/lo planes (4 slabs x [128][64B])
__device__ __forceinline__ void load_tile_planes(const float* __restrict__ gsrc,
                                                 char* hip, char* lop, int tid) {
#pragma unroll
    for (int i = 0; i < 8; i++) {
        const int t = tid + i * 256;           // 2048 tasks
        const int slab = t >> 9, rem = t & 511;
        const int row = rem >> 2, ch = rem & 3;
        const float* src = gsrc + (size_t)row * DH + slab * 32 + ch * 8;
        float4 f0 = *(const float4*)src;
        float4 f1 = *(const float4*)(src + 4);
        const int off = slab * 8192 + row * 64 + ((ch ^ ((row >> 1) & 3)) << 4);
        cvt_sts(f0, f1, hip + off, lop + off);
    }
}

// V [key][d] -> transposed planes V^T[d][key] (slabs over keys)
__device__ __forceinline__ void load_vt_planes(const float* __restrict__ gsrc,
                                               char* hip, char* lop, int tid) {
#pragma unroll
    for (int i = 0; i < 8; i++) {
        const int t = tid + i * 256;           // 2048 tasks
        const int dchunk = t >> 7, key = t & 127;
        const float* src = gsrc + (size_t)key * DH + dchunk * 8;
        float4 f0 = *(const float4*)src;
        float4 f1 = *(const float4*)(src + 4);
        float f[8] = {f0.x, f0.y, f0.z, f0.w, f1.x, f1.y, f1.z, f1.w};
        const int slab = key >> 5, kl = key & 31;
#pragma unroll
        for (int e = 0; e < 8; e++) {
            const int d = dchunk * 8 + e;
            __nv_bfloat16 h = __float2bfloat16_rn(f[e]);
            __nv_bfloat16 l = __float2bfloat16_rn(f[e] - __bfloat162float(h));
            const int addr = slab * 8192 + d * 64 +
                             (((kl >> 3) ^ ((d >> 1) & 3)) << 4) + (kl & 7) * 2;
            *(__nv_bfloat16*)(hip + addr) = h;
            *(__nv_bfloat16*)(lop + addr) = l;
        }
    }
}

__device__ __forceinline__ float red4max(float v) {
    v = fmaxf(v, __shfl_xor_sync(0xffffffffu, v, 1));
    v = fmaxf(v, __shfl_xor_sync(0xffffffffu, v, 2));
    return v;
}
__device__ __forceinline__ float red4sum(float v) {
    v += __shfl_xor_sync(0xffffffffu, v, 1);
    v += __shfl_xor_sync(0xffffffffu, v, 2);
    return v;
}

__global__ __launch_bounds__(256, 1) void flash_mma_kernel() {
    extern __shared__ char smem[];
    const int tid  = threadIdx.x;
    const int lane = tid & 31;
    const int w    = tid >> 5;
    const int h    = blockIdx.y;
    const int qb   = (int)gridDim.x - 1 - (int)blockIdx.x;  // heavy first
    const int q0   = qb * 128;
    const unsigned sbase = (unsigned)__cvta_generic_to_shared(smem);

    // resident Q planes
    load_tile_planes(g_q + ((size_t)h * SQ + q0) * DH,
                     smem + F_Q_HI, smem + F_Q_LO, tid);

    float sc[16][4];                 // S / P c-fragments
    float oc[16][4];                 // O c-fragments
#pragma unroll
    for (int nt = 0; nt < 16; nt++)
#pragma unroll
        for (int e = 0; e < 4; e++) oc[nt][e] = 0.f;
    float m0r = -1e30f, m1r = -1e30f, l0r = 0.f, l1r = 0.f;

    const float SCALE = 0.08838834764831845f;  // 1/sqrt(128)
    const int qg0 = q0 + w * 16 + (lane >> 2);
    const int qg1 = qg0 + 8;

    for (int ck = 0; ck <= qb; ck++) {
        load_tile_planes(g_k + ((size_t)h * SQ + ck * 128) * DH,
                         smem + F_K_HI, smem + F_K_LO, tid);
        load_vt_planes(g_v + ((size_t)h * SQ + ck * 128) * DH,
                       smem + F_V_HI, smem + F_V_LO, tid);
        __syncthreads();

        // ---- S = Q K^T (bf16x3) ----
#pragma unroll
        for (int nt = 0; nt < 16; nt++)
#pragma unroll
            for (int e = 0; e < 4; e++) sc[nt][e] = 0.f;

#pragma unroll
        for (int kst = 0; kst < 8; kst++) {
            const int slab = kst >> 1, ks = kst & 1;
            const int arow = w * 16 + (lane & 15);
            const int ach  = ks * 2 + (lane >> 4);
            const int aoff = slab * 8192 + arow * 64 +
                             ((ach ^ ((arow >> 1) & 3)) << 4);
            unsigned ahi[4], alo[4];
            ldsm4(ahi[0], ahi[1], ahi[2], ahi[3], sbase + F_Q_HI + aoff);
            ldsm4(alo[0], alo[1], alo[2], alo[3], sbase + F_Q_LO + aoff);
#pragma unroll
            for (int nt = 0; nt < 16; nt++) {
                const int brow = nt * 8 + (lane & 7);
                const int bch  = ks * 2 + ((lane >> 3) & 1);
                const int boff = slab * 8192 + brow * 64 +
                                 ((bch ^ ((brow >> 1) & 3)) << 4);
                unsigned bhi[2], blo[2];
                ldsm2(bhi[0], bhi[1], sbase + F_K_HI + boff);
                ldsm2(blo[0], blo[1], sbase + F_K_LO + boff);
                mma16816(sc[nt], ahi, bhi);
                mma16816(sc[nt], ahi, blo);
                mma16816(sc[nt], alo, bhi);
            }
        }

        // ---- scale, softcap, causal mask, online softmax (registers) ----
        const bool diag = (ck == qb);
        float mx0 = -1e30f, mx1 = -1e30f;
#pragma unroll
        for (int nt = 0; nt < 16; nt++) {
            const int nb = ck * 128 + nt * 8 + 2 * (lane & 3);
#pragma unroll
            for (int e = 0; e < 4; e++) {
                float v = sc[nt][e] * SCALE;
                v = 50.f * tanhf(v * 0.02f);
                if (diag) {
                    const int kg = nb + (e & 1);
                    const int qg = (e < 2) ? qg0 : qg1;
                    if (kg > qg) v = -1e30f;
                }
                sc[nt][e] = v;
                if (e < 2) mx0 = fmaxf(mx0, v); else mx1 = fmaxf(mx1, v);
            }
        }
        mx0 = red4max(mx0);  mx1 = red4max(mx1);
        const float nm0 = fmaxf(m0r, mx0), nm1 = fmaxf(m1r, mx1);
        const float a0  = __expf(m0r - nm0), a1 = __expf(m1r - nm1);
        float s0 = 0.f, s1 = 0.f;
#pragma unroll
        for (int nt = 0; nt < 16; nt++) {
            float p0 = __expf(sc[nt][0] - nm0); sc[nt][0] = p0; s0 += p0;
            float p1 = __expf(sc[nt][1] - nm0); sc[nt][1] = p1; s0 += p1;
            float p2 = __expf(sc[nt][2] - nm1); sc[nt][2] = p2; s1 += p2;
            float p3 = __expf(sc[nt][3] - nm1); sc[nt][3] = p3; s1 += p3;
        }
        s0 = red4sum(s0);  s1 = red4sum(s1);
        l0r = l0r * a0 + s0;  l1r = l1r * a1 + s1;
        m0r = nm0;  m1r = nm1;
#pragma unroll
        for (int nt = 0; nt < 16; nt++) {
            oc[nt][0] *= a0; oc[nt][1] *= a0;
            oc[nt][2] *= a1; oc[nt][3] *= a1;
        }

        // ---- O += P V  (P from registers: c-frag pair -> A-frag) ----
#pragma unroll
        for (int kst = 0; kst < 8; kst++) {
            unsigned phi[4], plo[4];
            split2(sc[2 * kst][0],     sc[2 * kst][1],     phi[0], plo[0]);
            split2(sc[2 * kst][2],     sc[2 * kst][3],     phi[1], plo[1]);
            split2(sc[2 * kst + 1][0], sc[2 * kst + 1][1], phi[2], plo[2]);
            split2(sc[2 * kst + 1][2], sc[2 * kst + 1][3], phi[3], plo[3]);
            const int slab = kst >> 1, ks = kst & 1;
#pragma unroll
            for (int nt = 0; nt < 16; nt++) {
                const int brow = nt * 8 + (lane & 7);
                const int bch  = ks * 2 + ((lane >> 3) & 1);
                const int boff = slab * 8192 + brow * 64 +
                                 ((bch ^ ((brow >> 1) & 3)) << 4);
                unsigned vhi[2], vlo[2];
                ldsm2(vhi[0], vhi[1], sbase + F_V_HI + boff);
                ldsm2(vlo[0], vlo[1], sbase + F_V_LO + boff);
                mma16816(oc[nt], phi, vhi);
                mma16816(oc[nt], phi, vlo);
                mma16816(oc[nt], plo, vhi);
            }
        }
        __syncthreads();   // before next iter overwrites K/V planes
    }

    // ---- epilogue: normalize, write to g_attn[S][H*DH] ----
    const float inv0 = 1.f / l0r, inv1 = 1.f / l1r;
    float* Og = g_attn + (size_t)(q0 + w * 16) * DM + h * DH;
    const int r0 = lane >> 2;
#pragma unroll
    for (int nt = 0; nt < 16; nt++) {
        const int n = nt * 8 + 2 * (lane & 3);
        *(float2*)&Og[(size_t)r0 * DM + n] =
            make_float2(oc[nt][0] * inv0, oc[nt][1] * inv0);
        *(float2*)&Og[(size_t)(r0 + 8) * DM + n] =
            make_float2(oc[nt][2] * inv1, oc[nt][3] * inv1);
    }
}

// ---------------- launch ----------------------------------------------------
extern "C" void kernel_launch(void* const* d_in, const int* in_sizes, int n_in,
                              void* d_out, int out_size) {
    (void)in_sizes; (void)n_in; (void)out_size;
    const float* x  = (const float*)d_in[0];
    const float* rc = (const float*)d_in[1];
    const float* rs = (const float*)d_in[2];
    // d_in[3] = mask: exactly causal -1e9; implemented directly in-kernel.
    const float* wq = (const float*)d_in[4];
    const float* wk = (const float*)d_in[5];
    const float* wv = (const float*)d_in[6];
    const float* wo = (const float*)d_in[7];
    float* out = (float*)d_out;

    cudaFuncSetAttribute(gemm_qkv, cudaFuncAttributeMaxDynamicSharedMemorySize,
                         GEMM_SMEM_BYTES);
    cudaFuncSetAttribute(gemm_out, cudaFuncAttributeMaxDynamicSharedMemorySize,
                         GEMM_SMEM_BYTES);
    cudaFuncSetAttribute(flash_mma_kernel,
                         cudaFuncAttributeMaxDynamicSharedMemorySize,
                         FLASH2_SMEM);

    gemm_qkv<<<dim3(16, 16, 3), 256, GEMM_SMEM_BYTES>>>(x, wq, wk, wv);
    rope_kernel<<<(2 * HN * SQ * 64) / 256, 256>>>(rc, rs);
    flash_mma_kernel<<<dim3(16, 16), 256, FLASH2_SMEM>>>();
    gemm_out<<<dim3(16, 16), 256, GEMM_SMEM_BYTES>>>(wo, out);
}

// round 16
// speedup vs baseline: 2.4967x; 1.2810x over previous
#include <cuda_runtime.h>
#include <cuda_bf16.h>
#include <math.h>
#include <float.h>

#define HN 16
#define SQ 2048
#define DM 2048
#define DH 128

// ---------------- scratch (static device arrays: no allocation allowed) ----
__device__ float g_q[HN * SQ * DH];     // head-major [H][S][DH]
__device__ float g_k[HN * SQ * DH];
__device__ float g_v[HN * SQ * DH];
__device__ float g_attn[SQ * DM];       // [S][H*DH] row-major

// pre-converted bf16 hi/lo planes (row-major [2048][2048])
__device__ __nv_bfloat16 g_x_hi[DM * DM],    g_x_lo[DM * DM];
__device__ __nv_bfloat16 g_wq_hi[DM * DM],   g_wq_lo[DM * DM];
__device__ __nv_bfloat16 g_wk_hi[DM * DM],   g_wk_lo[DM * DM];
__device__ __nv_bfloat16 g_wv_hi[DM * DM],   g_wv_lo[DM * DM];
__device__ __nv_bfloat16 g_wo_hi[DM * DM],   g_wo_lo[DM * DM];
__device__ __nv_bfloat16 g_at_hi[DM * DM],   g_at_lo[DM * DM];

// ============================================================================
// Common MMA / conversion primitives (bf16x3 split arithmetic)
// ============================================================================

__device__ __forceinline__ void ldsm4(unsigned& r0, unsigned& r1,
                                      unsigned& r2, unsigned& r3, unsigned addr) {
    asm volatile("ldmatrix.sync.aligned.m8n8.x4.shared.b16 {%0,%1,%2,%3}, [%4];"
                 : "=r"(r0), "=r"(r1), "=r"(r2), "=r"(r3) : "r"(addr));
}
__device__ __forceinline__ void ldsm2(unsigned& r0, unsigned& r1, unsigned addr) {
    asm volatile("ldmatrix.sync.aligned.m8n8.x2.shared.b16 {%0,%1}, [%2];"
                 : "=r"(r0), "=r"(r1) : "r"(addr));
}
__device__ __forceinline__ void mma16816(float c[4], const unsigned a[4],
                                         const unsigned b[2]) {
    asm volatile(
        "mma.sync.aligned.m16n8k16.row.col.f32.bf16.bf16.f32 "
        "{%0,%1,%2,%3}, {%4,%5,%6,%7}, {%8,%9}, {%0,%1,%2,%3};"
        : "+f"(c[0]), "+f"(c[1]), "+f"(c[2]), "+f"(c[3])
        : "r"(a[0]), "r"(a[1]), "r"(a[2]), "r"(a[3]), "r"(b[0]), "r"(b[1]));
}

// split two fp32 into packed bf16x2 hi and lo (x = hi + lo, split exact)
__device__ __forceinline__ void split2(float x0, float x1,
                                       unsigned& hi, unsigned& lo) {
    __nv_bfloat16 h0 = __float2bfloat16_rn(x0);
    __nv_bfloat16 h1 = __float2bfloat16_rn(x1);
    __nv_bfloat16 l0 = __float2bfloat16_rn(x0 - __bfloat162float(h0));
    __nv_bfloat16 l1 = __float2bfloat16_rn(x1 - __bfloat162float(h1));
    hi = (unsigned)__bfloat16_as_ushort(h0) |
         ((unsigned)__bfloat16_as_ushort(h1) << 16);
    lo = (unsigned)__bfloat16_as_ushort(l0) |
         ((unsigned)__bfloat16_as_ushort(l1) << 16);
}

// convert 8 fp32 -> 16B hi-plane + 16B lo-plane stores (flash uses this)
__device__ __forceinline__ void cvt_sts(const float4 f0, const float4 f1,
                                        char* hip, char* lop) {
    float f[8] = {f0.x, f0.y, f0.z, f0.w, f1.x, f1.y, f1.z, f1.w};
    unsigned h[4], l[4];
#pragma unroll
    for (int i = 0; i < 4; i++) split2(f[2 * i], f[2 * i + 1], h[i], l[i]);
    *(uint4*)hip = make_uint4(h[0], h[1], h[2], h[3]);
    *(uint4*)lop = make_uint4(l[0], l[1], l[2], l[3]);
}

#define CP16(saddr, gptr) \
    asm volatile("cp.async.cg.shared.global [%0], [%1], 16;" \
                 :: "r"(saddr), "l"(gptr))
#define CP_COMMIT() asm volatile("cp.async.commit_group;")
#define CP_WAIT0()  asm volatile("cp.async.wait_group 0;")

// ---------------- one-time fp32 -> bf16 hi/lo conversion --------------------
// 2048x2048 per matrix; each thread converts 4 floats. grid.x=4096, y=matrix.
__global__ __launch_bounds__(256) void cvt5_kernel(const float* __restrict__ x,
                                                   const float* __restrict__ wq,
                                                   const float* __restrict__ wk,
                                                   const float* __restrict__ wv,
                                                   const float* __restrict__ wo) {
    const float* s;
    __nv_bfloat16 *h, *l;
    switch (blockIdx.y) {
        case 0: s = x;  h = g_x_hi;  l = g_x_lo;  break;
        case 1: s = wq; h = g_wq_hi; l = g_wq_lo; break;
        case 2: s = wk; h = g_wk_hi; l = g_wk_lo; break;
        case 3: s = wv; h = g_wv_hi; l = g_wv_lo; break;
        default: s = wo; h = g_wo_hi; l = g_wo_lo; break;
    }
    const size_t i = ((size_t)blockIdx.x * 256 + threadIdx.x) * 4;
    float4 v = *(const float4*)(s + i);
    unsigned h0, l0, h1, l1;
    split2(v.x, v.y, h0, l0);
    split2(v.z, v.w, h1, l1);
    *(uint2*)(h + i) = make_uint2(h0, h1);
    *(uint2*)(l + i) = make_uint2(l0, l1);
}

__global__ __launch_bounds__(256) void cvt_attn_kernel() {
    const size_t i = ((size_t)blockIdx.x * 256 + threadIdx.x) * 4;
    float4 v = *(const float4*)(g_attn + i);
    unsigned h0, l0, h1, l1;
    split2(v.x, v.y, h0, l0);
    split2(v.z, v.w, h1, l1);
    *(uint2*)(g_at_hi + i) = make_uint2(h0, h1);
    *(uint2*)(g_at_lo + i) = make_uint2(l0, l1);
}

// ============================================================================
// bf16x3 tensor-core GEMM: C = A * B^T, M=N=K=2048, inputs pre-split bf16.
// CTA tile 128x128, BK=32, 256 threads = 8 warps (2 m x 4 n), warp tile 64x32.
// Smem planes: [128 rows][32 bf16 = 64B], 16B chunks XOR-swizzled:
// phys_chunk = chunk ^ ((row>>1)&3). Double buffered (64KB), fed by cp.async.
// ============================================================================

#define STAGE_BYTES 32768
#define PLANE_A_HI 0
#define PLANE_A_LO 8192
#define PLANE_B_HI 16384
#define PLANE_B_LO 24576
#define GEMM_SMEM_BYTES (2 * STAGE_BYTES)

// HEAD=true: scatter C[m][n] to dst[h][m][jj], h=n>>7, jj=n&127.
template <bool HEAD>
__device__ __forceinline__ void gemm_body_mma(
    const __nv_bfloat16* __restrict__ Ah, const __nv_bfloat16* __restrict__ Al,
    const __nv_bfloat16* __restrict__ Bh, const __nv_bfloat16* __restrict__ Bl,
    float* __restrict__ dst) {
    extern __shared__ char smem[];
    const int tid  = threadIdx.x;
    const int lane = tid & 31;
    const int w    = tid >> 5;
    const int wm   = w & 1;        // 2 warps along M
    const int wn   = w >> 1;       // 4 warps along N
    const int m0   = blockIdx.y * 128;
    const int n0   = blockIdx.x * 128;

    // loader: two (row, 16B-chunk) tasks per matrix per thread
    const int r0 = tid >> 2,          c0 = tid & 3;
    const int r1 = (tid + 256) >> 2,  c1 = (tid + 256) & 3;
    const size_t offA0 = (size_t)(m0 + r0) * DM + c0 * 8;  // elements
    const size_t offA1 = (size_t)(m0 + r1) * DM + c1 * 8;
    const size_t offB0 = (size_t)(n0 + r0) * DM + c0 * 8;
    const size_t offB1 = (size_t)(n0 + r1) * DM + c1 * 8;
    const int so0 = r0 * 64 + ((c0 ^ ((r0 >> 1) & 3)) << 4);
    const int so1 = r1 * 64 + ((c1 ^ ((r1 >> 1) & 3)) << 4);

    float acc[4][4][4];
#pragma unroll
    for (int i = 0; i < 4; i++)
#pragma unroll
        for (int j = 0; j < 4; j++)
#pragma unroll
            for (int k = 0; k < 4; k++) acc[i][j][k] = 0.f;

    const unsigned sbase = (unsigned)__cvta_generic_to_shared(smem);

    // prologue: issue slab 0 into stage 0
    {
        const unsigned d = sbase;
        CP16(d + PLANE_A_HI + so0, Ah + offA0);
        CP16(d + PLANE_A_LO + so0, Al + offA0);
        CP16(d + PLANE_B_HI + so0, Bh + offB0);
        CP16(d + PLANE_B_LO + so0, Bl + offB0);
        CP16(d + PLANE_A_HI + so1, Ah + offA1);
        CP16(d + PLANE_A_LO + so1, Al + offA1);
        CP16(d + PLANE_B_HI + so1, Bh + offB1);
        CP16(d + PLANE_B_LO + so1, Bl + offB1);
        CP_COMMIT();
    }

    for (int k0 = 0; k0 < DM; k0 += 32) {
        const int  s    = (k0 >> 5) & 1;
        const bool more = (k0 + 32) < DM;

        // wait for stage s data; barrier also orders previous compute reads
        // of stage s^1 before we overwrite it below.
        CP_WAIT0();
        __syncthreads();

        if (more) {
            const unsigned d = sbase + (s ^ 1) * STAGE_BYTES;
            const int kn = k0 + 32;
            CP16(d + PLANE_A_HI + so0, Ah + offA0 + kn);
            CP16(d + PLANE_A_LO + so0, Al + offA0 + kn);
            CP16(d + PLANE_B_HI + so0, Bh + offB0 + kn);
            CP16(d + PLANE_B_LO + so0, Bl + offB0 + kn);
            CP16(d + PLANE_A_HI + so1, Ah + offA1 + kn);
            CP16(d + PLANE_A_LO + so1, Al + offA1 + kn);
            CP16(d + PLANE_B_HI + so1, Bh + offB1 + kn);
            CP16(d + PLANE_B_LO + so1, Bl + offB1 + kn);
            CP_COMMIT();
        }

        const unsigned sA = sbase + s * STAGE_BYTES;
#pragma unroll
        for (int ks = 0; ks < 2; ks++) {
            unsigned bhi[4][2], blo[4][2];
#pragma unroll
            for (int nt = 0; nt < 4; nt++) {
                const int row = wn * 32 + nt * 8 + (lane & 7);
                const int ch  = ks * 2 + ((lane >> 3) & 1);
                const int off = row * 64 + ((ch ^ ((row >> 1) & 3)) << 4);
                ldsm2(bhi[nt][0], bhi[nt][1], sA + PLANE_B_HI + off);
                ldsm2(blo[nt][0], blo[nt][1], sA + PLANE_B_LO + off);
            }
#pragma unroll
            for (int mt = 0; mt < 4; mt++) {
                const int row = wm * 64 + mt * 16 + (lane & 15);
                const int ch  = ks * 2 + (lane >> 4);
                const int off = row * 64 + ((ch ^ ((row >> 1) & 3)) << 4);
                unsigned ahi[4], alo[4];
                ldsm4(ahi[0], ahi[1], ahi[2], ahi[3], sA + PLANE_A_HI + off);
                ldsm4(alo[0], alo[1], alo[2], alo[3], sA + PLANE_A_LO + off);
#pragma unroll
                for (int nt = 0; nt < 4; nt++) {
                    mma16816(acc[mt][nt], ahi, bhi[nt]);
                    mma16816(acc[mt][nt], ahi, blo[nt]);
                    mma16816(acc[mt][nt], alo, bhi[nt]);
                }
            }
        }
    }

    // epilogue: c0,c1 -> (row, n..n+1); c2,c3 -> (row+8, n..n+1)
#pragma unroll
    for (int mt = 0; mt < 4; mt++) {
        const int row = m0 + wm * 64 + mt * 16 + (lane >> 2);
#pragma unroll
        for (int nt = 0; nt < 4; nt++) {
            const int n = n0 + wn * 32 + nt * 8 + 2 * (lane & 3);
            const float2 v01 = make_float2(acc[mt][nt][0], acc[mt][nt][1]);
            const float2 v23 = make_float2(acc[mt][nt][2], acc[mt][nt][3]);
            if (HEAD) {
                const int h = n >> 7, jj = n & 127;
                *(float2*)&dst[((size_t)h * SQ + row) * DH + jj]     = v01;
                *(float2*)&dst[((size_t)h * SQ + row + 8) * DH + jj] = v23;
            } else {
                *(float2*)&dst[(size_t)row * DM + n]       = v01;
                *(float2*)&dst[(size_t)(row + 8) * DM + n] = v23;
            }
        }
    }
}

__global__ __launch_bounds__(256, 2) void gemm_qkv(const float* __restrict__ x) {
    (void)x;
    const int z = blockIdx.z;
    const __nv_bfloat16* Bh = (z == 0) ? g_wq_hi : (z == 1) ? g_wk_hi : g_wv_hi;
    const __nv_bfloat16* Bl = (z == 0) ? g_wq_lo : (z == 1) ? g_wk_lo : g_wv_lo;
    float* dst              = (z == 0) ? g_q     : (z == 1) ? g_k     : g_v;
    gemm_body_mma<true>(g_x_hi, g_x_lo, Bh, Bl, dst);
}

__global__ __launch_bounds__(256, 2) void gemm_out(float* __restrict__ out) {
    gemm_body_mma<false>(g_at_hi, g_at_lo, g_wo_hi, g_wo_lo, out);
}

// ---------------- RoPE (in-place on g_q, g_k) ------------------------------
__global__ void rope_kernel(const float* __restrict__ cosp,
                            const float* __restrict__ sinp) {
    const int idx = blockIdx.x * blockDim.x + threadIdx.x;
    const int j     = idx & 63;
    const int s     = (idx >> 6) & (SQ - 1);
    const int h     = (idx >> 17) & 15;
    const int which = idx >> 21;
    float* p = (which ? g_k : g_q) + ((size_t)h * SQ + s) * DH;
    const float c  = cosp[s * DH + j];
    const float sn = sinp[s * DH + j];
    const float x1 = p[j], x2 = p[j + 64];
    p[j]      = x1 * c - x2 * sn;
    p[j + 64] = x2 * c + x1 * sn;
}

// ============================================================================
// Tensor-core flash attention (causal, tanh softcap 50), bf16x3 on S and PV.
// (unchanged from R12 — HW-validated)
// ============================================================================

#define F_Q_HI 0
#define F_Q_LO 32768
#define F_K_HI 65536
#define F_K_LO 98304
#define F_V_HI 131072
#define F_V_LO 163840
#define FLASH2_SMEM 196608

__device__ __forceinline__ void load_tile_planes(const float* __restrict__ gsrc,
                                                 char* hip, char* lop, int tid) {
#pragma unroll
    for (int i = 0; i < 8; i++) {
        const int t = tid + i * 256;
        const int slab = t >> 9, rem = t & 511;
        const int row = rem >> 2, ch = rem & 3;
        const float* src = gsrc + (size_t)row * DH + slab * 32 + ch * 8;
        float4 f0 = *(const float4*)src;
        float4 f1 = *(const float4*)(src + 4);
        const int off = slab * 8192 + row * 64 + ((ch ^ ((row >> 1) & 3)) << 4);
        cvt_sts(f0, f1, hip + off, lop + off);
    }
}

__device__ __forceinline__ void load_vt_planes(const float* __restrict__ gsrc,
                                               char* hip, char* lop, int tid) {
#pragma unroll
    for (int i = 0; i < 8; i++) {
        const int t = tid + i * 256;
        const int dchunk = t >> 7, key = t & 127;
        const float* src = gsrc + (size_t)key * DH + dchunk * 8;
        float4 f0 = *(const float4*)src;
        float4 f1 = *(const float4*)(src + 4);
        float f[8] = {f0.x, f0.y, f0.z, f0.w, f1.x, f1.y, f1.z, f1.w};
        const int slab = key >> 5, kl = key & 31;
#pragma unroll
        for (int e = 0; e < 8; e++) {
            const int d = dchunk * 8 + e;
            __nv_bfloat16 h = __float2bfloat16_rn(f[e]);
            __nv_bfloat16 l = __float2bfloat16_rn(f[e] - __bfloat162float(h));
            const int addr = slab * 8192 + d * 64 +
                             (((kl >> 3) ^ ((d >> 1) & 3)) << 4) + (kl & 7) * 2;
            *(__nv_bfloat16*)(hip + addr) = h;
            *(__nv_bfloat16*)(lop + addr) = l;
        }
    }
}

__device__ __forceinline__ float red4max(float v) {
    v = fmaxf(v, __shfl_xor_sync(0xffffffffu, v, 1));
    v = fmaxf(v, __shfl_xor_sync(0xffffffffu, v, 2));
    return v;
}
__device__ __forceinline__ float red4sum(float v) {
    v += __shfl_xor_sync(0xffffffffu, v, 1);
    v += __shfl_xor_sync(0xffffffffu, v, 2);
    return v;
}

__global__ __launch_bounds__(256, 1) void flash_mma_kernel() {
    extern __shared__ char smem[];
    const int tid  = threadIdx.x;
    const int lane = tid & 31;
    const int w    = tid >> 5;
    const int h    = blockIdx.y;
    const int qb   = (int)gridDim.x - 1 - (int)blockIdx.x;  // heavy first
    const int q0   = qb * 128;
    const unsigned sbase = (unsigned)__cvta_generic_to_shared(smem);

    load_tile_planes(g_q + ((size_t)h * SQ + q0) * DH,
                     smem + F_Q_HI, smem + F_Q_LO, tid);

    float sc[16][4];
    float oc[16][4];
#pragma unroll
    for (int nt = 0; nt < 16; nt++)
#pragma unroll
        for (int e = 0; e < 4; e++) oc[nt][e] = 0.f;
    float m0r = -1e30f, m1r = -1e30f, l0r = 0.f, l1r = 0.f;

    const float SCALE = 0.08838834764831845f;  // 1/sqrt(128)
    const int qg0 = q0 + w * 16 + (lane >> 2);
    const int qg1 = qg0 + 8;

    for (int ck = 0; ck <= qb; ck++) {
        load_tile_planes(g_k + ((size_t)h * SQ + ck * 128) * DH,
                         smem + F_K_HI, smem + F_K_LO, tid);
        load_vt_planes(g_v + ((size_t)h * SQ + ck * 128) * DH,
                       smem + F_V_HI, smem + F_V_LO, tid);
        __syncthreads();

#pragma unroll
        for (int nt = 0; nt < 16; nt++)
#pragma unroll
            for (int e = 0; e < 4; e++) sc[nt][e] = 0.f;

#pragma unroll
        for (int kst = 0; kst < 8; kst++) {
            const int slab = kst >> 1, ks = kst & 1;
            const int arow = w * 16 + (lane & 15);
            const int ach  = ks * 2 + (lane >> 4);
            const int aoff = slab * 8192 + arow * 64 +
                             ((ach ^ ((arow >> 1) & 3)) << 4);
            unsigned ahi[4], alo[4];
            ldsm4(ahi[0], ahi[1], ahi[2], ahi[3], sbase + F_Q_HI + aoff);
            ldsm4(alo[0], alo[1], alo[2], alo[3], sbase + F_Q_LO + aoff);
#pragma unroll
            for (int nt = 0; nt < 16; nt++) {
                const int brow = nt * 8 + (lane & 7);
                const int bch  = ks * 2 + ((lane >> 3) & 1);
                const int boff = slab * 8192 + brow * 64 +
                                 ((bch ^ ((brow >> 1) & 3)) << 4);
                unsigned bhi[2], blo[2];
                ldsm2(bhi[0], bhi[1], sbase + F_K_HI + boff);
                ldsm2(blo[0], blo[1], sbase + F_K_LO + boff);
                mma16816(sc[nt], ahi, bhi);
                mma16816(sc[nt], ahi, blo);
                mma16816(sc[nt], alo, bhi);
            }
        }

        const bool diag = (ck == qb);
        float mx0 = -1e30f, mx1 = -1e30f;
#pragma unroll
        for (int nt = 0; nt < 16; nt++) {
            const int nb = ck * 128 + nt * 8 + 2 * (lane & 3);
#pragma unroll
            for (int e = 0; e < 4; e++) {
                float v = sc[nt][e] * SCALE;
                v = 50.f * tanhf(v * 0.02f);
                if (diag) {
                    const int kg = nb + (e & 1);
                    const int qg = (e < 2) ? qg0 : qg1;
                    if (kg > qg) v = -1e30f;
                }
                sc[nt][e] = v;
                if (e < 2) mx0 = fmaxf(mx0, v); else mx1 = fmaxf(mx1, v);
            }
        }
        mx0 = red4max(mx0);  mx1 = red4max(mx1);
        const float nm0 = fmaxf(m0r, mx0), nm1 = fmaxf(m1r, mx1);
        const float a0  = __expf(m0r - nm0), a1 = __expf(m1r - nm1);
        float s0 = 0.f, s1 = 0.f;
#pragma unroll
        for (int nt = 0; nt < 16; nt++) {
            float p0 = __expf(sc[nt][0] - nm0); sc[nt][0] = p0; s0 += p0;
            float p1 = __expf(sc[nt][1] - nm0); sc[nt][1] = p1; s0 += p1;
            float p2 = __expf(sc[nt][2] - nm1); sc[nt][2] = p2; s1 += p2;
            float p3 = __expf(sc[nt][3] - nm1); sc[nt][3] = p3; s1 += p3;
        }
        s0 = red4sum(s0);  s1 = red4sum(s1);
        l0r = l0r * a0 + s0;  l1r = l1r * a1 + s1;
        m0r = nm0;  m1r = nm1;
#pragma unroll
        for (int nt = 0; nt < 16; nt++) {
            oc[nt][0] *= a0; oc[nt][1] *= a0;
            oc[nt][2] *= a1; oc[nt][3] *= a1;
        }

#pragma unroll
        for (int kst = 0; kst < 8; kst++) {
            unsigned phi[4], plo[4];
            split2(sc[2 * kst][0],     sc[2 * kst][1],     phi[0], plo[0]);
            split2(sc[2 * kst][2],     sc[2 * kst][3],     phi[1], plo[1]);
            split2(sc[2 * kst + 1][0], sc[2 * kst + 1][1], phi[2], plo[2]);
            split2(sc[2 * kst + 1][2], sc[2 * kst + 1][3], phi[3], plo[3]);
            const int slab = kst >> 1, ks = kst & 1;
#pragma unroll
            for (int nt = 0; nt < 16; nt++) {
                const int brow = nt * 8 + (lane & 7);
                const int bch  = ks * 2 + ((lane >> 3) & 1);
                const int boff = slab * 8192 + brow * 64 +
                                 ((bch ^ ((brow >> 1) & 3)) << 4);
                unsigned vhi[2], vlo[2];
                ldsm2(vhi[0], vhi[1], sbase + F_V_HI + boff);
                ldsm2(vlo[0], vlo[1], sbase + F_V_LO + boff);
                mma16816(oc[nt], phi, vhi);
                mma16816(oc[nt], phi, vlo);
                mma16816(oc[nt], plo, vhi);
            }
        }
        __syncthreads();
    }

    const float inv0 = 1.f / l0r, inv1 = 1.f / l1r;
    float* Og = g_attn + (size_t)(q0 + w * 16) * DM + h * DH;
    const int r0 = lane >> 2;
#pragma unroll
    for (int nt = 0; nt < 16; nt++) {
        const int n = nt * 8 + 2 * (lane & 3);
        *(float2*)&Og[(size_t)r0 * DM + n] =
            make_float2(oc[nt][0] * inv0, oc[nt][1] * inv0);
        *(float2*)&Og[(size_t)(r0 + 8) * DM + n] =
            make_float2(oc[nt][2] * inv1, oc[nt][3] * inv1);
    }
}

// ---------------- launch ----------------------------------------------------
extern "C" void kernel_launch(void* const* d_in, const int* in_sizes, int n_in,
                              void* d_out, int out_size) {
    (void)in_sizes; (void)n_in; (void)out_size;
    const float* x  = (const float*)d_in[0];
    const float* rc = (const float*)d_in[1];
    const float* rs = (const float*)d_in[2];
    // d_in[3] = mask: exactly causal -1e9; implemented directly in-kernel.
    const float* wq = (const float*)d_in[4];
    const float* wk = (const float*)d_in[5];
    const float* wv = (const float*)d_in[6];
    const float* wo = (const float*)d_in[7];
    float* out = (float*)d_out;

    cudaFuncSetAttribute(gemm_qkv, cudaFuncAttributeMaxDynamicSharedMemorySize,
                         GEMM_SMEM_BYTES);
    cudaFuncSetAttribute(gemm_out, cudaFuncAttributeMaxDynamicSharedMemorySize,
                         GEMM_SMEM_BYTES);
    cudaFuncSetAttribute(flash_mma_kernel,
                         cudaFuncAttributeMaxDynamicSharedMemorySize,
                         FLASH2_SMEM);

    // one-time conversions (x, wq, wk, wv, wo)
    cvt5_kernel<<<dim3(DM * DM / (256 * 4), 5), 256>>>(x, wq, wk, wv, wo);

    gemm_qkv<<<dim3(16, 16, 3), 256, GEMM_SMEM_BYTES>>>(x);
    rope_kernel<<<(2 * HN * SQ * 64) / 256, 256>>>(rc, rs);
    flash_mma_kernel<<<dim3(16, 16), 256, FLASH2_SMEM>>>();
    cvt_attn_kernel<<<DM * DM / (256 * 4), 256>>>();
    gemm_out<<<dim3(16, 16), 256, GEMM_SMEM_BYTES>>>(out);
}